// round 14
// baseline (speedup 1.0000x reference)
#include <cuda_runtime.h>
#include <float.h>
#include <math.h>
#include <stdint.h>

// Problem constants
#define NPTS 12288
#define DIM 64
#define KNN 16
#define EPS 1e-5f
#define DIAG_BIAS 1e6f

// Tiling: 256 threads (8 warps x m16), BI=128 rows, BJ=64 cols per tile
#define THREADS 256
#define BI 128
#define BJ 64
#define NSEG 3
#define SEGJ (NPTS / NSEG)        // 4096
#define NTILES (SEGJ / BJ)        // 64
#define NROWBLK (NPTS / BI)       // 96
#define CPSEG 64                  // pair-entries emitted per (row, segment)
#define NCAND (NSEG * CPSEG)      // 192 pair-entries per row (384 candidates)
#define RSUB 8                    // rescore sub-threads per row

// smem layout (floats). sj holds hi-only j-tiles, permuted k order: [col][64].
#define SJ_STRIDE 72
#define SJ_BUF (BJ * SJ_STRIDE)                      // 4608
#define SSQJ_OFF (2 * SJ_BUF)                        // 9216
#define SMEM_FLOATS (SSQJ_OFF + 2 * BJ)              // 9344
#define SMEM_BYTES (SMEM_FLOATS * 4)                 // 37376

// Scratch (no allocations -> device globals)
__device__ float  g_hi[NPTS * DIM];   // tf32-rounded coords, permuted k order
__device__ float  g_sq[NPTS];
__device__ float  g_colsum[DIM];
__device__ double g_part[48];
__device__ float  g_sigma_inv;
__device__ int    g_cand[NPTS * NCAND];

typedef unsigned long long u64;

__device__ __forceinline__ uint32_t sptr(const void* p) {
    return (uint32_t)__cvta_generic_to_shared(p);
}
__device__ __forceinline__ void cp_async16(uint32_t dst, const void* src) {
    asm volatile("cp.async.cg.shared.global [%0], [%1], 16;" :: "r"(dst), "l"(src));
}
__device__ __forceinline__ void cp_async4(uint32_t dst, const void* src) {
    asm volatile("cp.async.ca.shared.global [%0], [%1], 4;" :: "r"(dst), "l"(src));
}
#define CP_COMMIT() asm volatile("cp.async.commit_group;")
#define CP_WAIT0()  asm volatile("cp.async.wait_group 0;")

// packed fp32x2 fma (R2's exact-scoring instruction)
__device__ __forceinline__ u64 ffma2(u64 a, u64 b, u64 c) {
    u64 d;
    asm("fma.rn.f32x2 %0, %1, %2, %3;" : "=l"(d) : "l"(a), "l"(b), "l"(c));
    return d;
}
__device__ __forceinline__ float pairsum(u64 a) {
    float lo = __uint_as_float((unsigned)(a & 0xffffffffull));
    float hi = __uint_as_float((unsigned)(a >> 32));
    return lo + hi;
}

// m16n8k8 tf32 mma: D = A*B + D (row-major A, col-major B), fp32 accum
__device__ __forceinline__ void mma_tf32(float (&c)[4], const uint32_t* a,
                                         uint32_t b0, uint32_t b1) {
    asm volatile(
        "mma.sync.aligned.m16n8k8.row.col.f32.tf32.tf32.f32 "
        "{%0,%1,%2,%3}, {%4,%5,%6,%7}, {%8,%9}, {%0,%1,%2,%3};"
        : "+f"(c[0]), "+f"(c[1]), "+f"(c[2]), "+f"(c[3])
        : "r"(a[0]), "r"(a[1]), "r"(a[2]), "r"(a[3]), "r"(b0), "r"(b1));
}

// ---------------------------------------------------------------------------
// Prologue: tf32-round coords into g_hi with permuted k order.
// ---------------------------------------------------------------------------
__global__ void hi_kernel(const float* __restrict__ coords) {
    int i = blockIdx.x * 256 + threadIdx.x;   // 0 .. NPTS*DIM-1
    int row = i >> 6, k = i & 63;
    int kc = k >> 3, r = k & 7;
    int pos = kc * 8 + (r & 3) * 2 + (r >> 2);
    float x = coords[i];
    uint32_t h;
    asm("cvt.rna.tf32.f32 %0, %1;" : "=r"(h) : "f"(x));
    g_hi[row * DIM + pos] = __uint_as_float(h);
}

// ---------------------------------------------------------------------------
__global__ void sq_kernel(const float* __restrict__ coords) {
    int row = blockIdx.x * 256 + threadIdx.x;
    const float4* p = (const float4*)(coords + (size_t)row * DIM);
    float s = 0.f;
#pragma unroll
    for (int t = 0; t < DIM / 4; ++t) {
        float4 v = p[t];
        s += v.x * v.x + v.y * v.y + v.z * v.z + v.w * v.w;
    }
    g_sq[row] = s;
}

__global__ void colsum_kernel(const float* __restrict__ coords) {
    __shared__ float red[256];
    int d = blockIdx.x;
    float s = 0.f;
    for (int r = threadIdx.x; r < NPTS; r += 256)
        s += coords[(size_t)r * DIM + d];
    red[threadIdx.x] = s;
    __syncthreads();
    for (int off = 128; off > 0; off >>= 1) {
        if (threadIdx.x < off) red[threadIdx.x] += red[threadIdx.x + off];
        __syncthreads();
    }
    if (threadIdx.x == 0) g_colsum[d] = red[0];
}

// 48 partial double sums of g_sq (deterministic tree per block)
__global__ void sqsum_kernel() {
    __shared__ double red[256];
    double s = (double)g_sq[blockIdx.x * 256 + threadIdx.x];
    red[threadIdx.x] = s;
    __syncthreads();
    for (int off = 128; off > 0; off >>= 1) {
        if (threadIdx.x < off) red[threadIdx.x] += red[threadIdx.x + off];
        __syncthreads();
    }
    if (threadIdx.x == 0) g_part[blockIdx.x] = red[0];
}

__global__ void sigma_final_kernel() {
    if (threadIdx.x == 0) {
        double sumsq = 0.0;
        for (int i = 0; i < 48; ++i) sumsq += g_part[i];
        double nrm2 = 0.0;
        for (int d = 0; d < DIM; ++d) {
            double c = (double)g_colsum[d];
            nrm2 += c * c;
        }
        const double Nd = (double)NPTS;
        double total = 2.0 * Nd * sumsq - 2.0 * nrm2
                     + Nd * Nd * (double)EPS + Nd * (double)DIAG_BIAS;
        double sigma2 = total / (Nd * Nd);
        g_sigma_inv = (float)(1.0 / (sigma2 + (double)EPS));
    }
}

// lexicographic (value, index) sorted insert (exact selection semantics)
__device__ __forceinline__ void topk_insert_tie(float (&vals)[KNN],
                                                int (&idx)[KNN],
                                                float v, int id) {
#pragma unroll
    for (int t = 0; t < KNN; ++t) {
        bool lt = (v < vals[t]) || (v == vals[t] && id < idx[t]);
        if (lt) {
            float tv = vals[t]; vals[t] = v; v = tv;
            int   ti = idx[t];  idx[t]  = id; id = ti;
        }
    }
}

// register key-list insert: sorted ascending, 16 deep, straight min/max chain
// (the R12 form -- no data-dependent branches). Caller guarantees k < ks[15].
__device__ __forceinline__ void key_insert(uint32_t (&ks)[16], uint32_t k) {
#pragma unroll
    for (int t = 0; t < 16; ++t) {
        uint32_t cur = ks[t];
        uint32_t lo = (k < cur) ? k : cur;
        uint32_t hi = (k < cur) ? cur : k;
        ks[t] = lo;
        k = hi;
    }
}

// ---------------------------------------------------------------------------
// Stage one 64-row hi-only j-tile (256B per row, direct copy of g_hi rows).
// ---------------------------------------------------------------------------
__device__ __forceinline__ void issue_jtile(int jbase, float* sjb,
                                            float* ssqjb, int tid) {
    int r = tid >> 2;        // 0..63 tile row
    int c4 = tid & 3;
    const float* src = g_hi + (size_t)(jbase + r) * DIM;
    float* dst = sjb + r * SJ_STRIDE;
#pragma unroll
    for (int m = 0; m < 4; ++m) {
        int ch = c4 + m * 4;  // 16B chunk 0..15
        cp_async16(sptr(dst + ch * 4), src + ch * 4);
    }
    if (tid < BJ) cp_async4(sptr(ssqjb + tid), &g_sq[jbase + tid]);
}

// ---------------------------------------------------------------------------
// Kernel B: single-tf32 tensor-core distance tiles + register-packed top-16
// over COLUMN-PAIR MINIMA. Top-16 pairs provably contain all top-16 singles
// (each pair ahead of x's pair holds an element < x; at most 15 exist).
// ---------------------------------------------------------------------------
__global__ void __launch_bounds__(THREADS, 2)
knn_mma_kernel() {
    extern __shared__ float smem[];
    float* sj   = smem;
    float* ssqj = smem + SSQJ_OFF;

    const int tid = threadIdx.x;
    const int w = tid >> 5, l = tid & 31;
    const int g = l >> 2, t = l & 3;
    const int row0 = blockIdx.x * BI;
    const int jseg = blockIdx.y * SEGJ;
    const int rowA0 = row0 + w * 16 + g;
    const int rowA1 = rowA0 + 8;

    // warp-uniform: the single tile (if any) containing this warp's diagonal
    int diagTile = -1;
    if (rowA0 >= jseg && rowA0 < jseg + SEGJ) diagTile = (rowA0 - jseg) >> 6;

    uint32_t key0[16], key1[16];
#pragma unroll
    for (int k = 0; k < 16; ++k) { key0[k] = 0xFFFFFFFFu; key1[k] = 0xFFFFFFFFu; }

    // A fragments (persistent, hi only)
    uint32_t ah[32];
#pragma unroll
    for (int kc = 0; kc < 8; ++kc) {
        float2 p0 = *(const float2*)&g_hi[(size_t)rowA0 * DIM + kc * 8 + 2 * t];
        float2 p1 = *(const float2*)&g_hi[(size_t)rowA1 * DIM + kc * 8 + 2 * t];
        ah[kc * 4 + 0] = __float_as_uint(p0.x);
        ah[kc * 4 + 1] = __float_as_uint(p1.x);
        ah[kc * 4 + 2] = __float_as_uint(p0.y);
        ah[kc * 4 + 3] = __float_as_uint(p1.y);
    }
    const float sqi0e = g_sq[rowA0] + EPS;
    const float sqi1e = g_sq[rowA1] + EPS;

    issue_jtile(jseg, sj, ssqj, tid);
    CP_COMMIT();

    int buf = 0;
    for (int tile = 0; tile < NTILES; ++tile) {
        const int jbase = jseg + tile * BJ;
        CP_WAIT0();
        __syncthreads();

        if (tile + 1 < NTILES) {
            issue_jtile(jbase + BJ, sj + (buf ^ 1) * SJ_BUF,
                        ssqj + (buf ^ 1) * BJ, tid);
            CP_COMMIT();
        }

        const float* sjb = sj + buf * SJ_BUF;
        const float* ssqjb = ssqj + buf * BJ;
        const bool diagHere = (tile == diagTile);
#pragma unroll
        for (int nt2 = 0; nt2 < 4; ++nt2) {
            float c0[4] = {0.f, 0.f, 0.f, 0.f};
            float c1[4] = {0.f, 0.f, 0.f, 0.f};
            const float* b0p = sjb + (nt2 * 16 + g) * SJ_STRIDE + 2 * t;
            const float* b1p = sjb + (nt2 * 16 + 8 + g) * SJ_STRIDE + 2 * t;
#pragma unroll
            for (int kc = 0; kc < 8; ++kc) {
                float2 b0 = *(const float2*)(b0p + kc * 8);  // (k=t, k=t+4)
                float2 b1 = *(const float2*)(b1p + kc * 8);
                mma_tf32(c0, ah + kc * 4, __float_as_uint(b0.x), __float_as_uint(b0.y));
                mma_tf32(c1, ah + kc * 4, __float_as_uint(b1.x), __float_as_uint(b1.y));
            }
#pragma unroll
            for (int h = 0; h < 2; ++h) {
                const float* c = h ? c1 : c0;
                const int nt = nt2 * 2 + h;
                const int colb = nt * 8 + 2 * t;
                float2 sqj2 = *(const float2*)(ssqjb + colb);
                float d0 = fmaf(-2.f, c[0], sqi0e + sqj2.x);
                float d1 = fmaf(-2.f, c[1], sqi0e + sqj2.y);
                float d2 = fmaf(-2.f, c[2], sqi1e + sqj2.x);
                float d3 = fmaf(-2.f, c[3], sqi1e + sqj2.y);
                if (diagHere) {           // warp-uniform, one tile per segment
                    const int col0 = jbase + colb;
                    if (rowA0 == col0)     d0 += DIAG_BIAS;
                    if (rowA0 == col0 + 1) d1 += DIAG_BIAS;
                    if (rowA1 == col0)     d2 += DIAG_BIAS;
                    if (rowA1 == col0 + 1) d3 += DIAG_BIAS;
                }
                const uint32_t cin0 = (uint32_t)(tile * BJ + colb);  // even
                uint32_t k0 = (__float_as_uint(fminf(d0, d1)) & 0xFFFFF000u) | cin0;
                if (k0 < key0[15]) key_insert(key0, k0);
                uint32_t k1 = (__float_as_uint(fminf(d2, d3)) & 0xFFFFF000u) | cin0;
                if (k1 < key1[15]) key_insert(key1, k1);
            }
        }
        buf ^= 1;
    }

    // ---- emit pair-base columns (4 lanes x 16 pairs per row-segment) ----
    {
        const size_t o0 = ((size_t)rowA0 * NSEG + blockIdx.y) * CPSEG + t * 16;
        const size_t o1 = ((size_t)rowA1 * NSEG + blockIdx.y) * CPSEG + t * 16;
#pragma unroll
        for (int k = 0; k < 16; ++k) {
            g_cand[o0 + k] = jseg + (int)(key0[k] & 0xFFFu);
            g_cand[o1 + k] = jseg + (int)(key1[k] & 0xFFFu);
        }
    }
}

// ---------------------------------------------------------------------------
// Kernel C: exact rescore. 8 sub-threads per row, each scoring 24 pair-entries
// (48 candidates) with R2's EXACT arithmetic; self-column guarded by
// DIAG_BIAS (pairs may reintroduce it). Exact lexicographic merge in smem.
// ---------------------------------------------------------------------------
__global__ void __launch_bounds__(128)
rescore_lap_kernel(const float* __restrict__ coords,
                   const float* __restrict__ potential,
                   float* __restrict__ out) {
    __shared__ float sv[16 * RSUB * KNN];   // 2048 floats
    __shared__ int   sx[16 * RSUB * KNN];

    const int rloc = threadIdx.x >> 3;    // 0..15
    const int sub  = threadIdx.x & (RSUB - 1);
    const int row  = blockIdx.x * 16 + rloc;

    u64 xi2[DIM / 2];
    {
        const u64* p = (const u64*)(coords + (size_t)row * DIM);
#pragma unroll
        for (int s = 0; s < DIM / 2; ++s) xi2[s] = p[s];
    }
    const float base_i = g_sq[row] + EPS;

    float vals[KNN];
    int   idx[KNN];
#pragma unroll
    for (int t = 0; t < KNN; ++t) { vals[t] = FLT_MAX; idx[t] = 0x7fffffff; }

    const size_t cbase = (size_t)row * NCAND + sub * (NCAND / RSUB);
#pragma unroll 1
    for (int c = 0; c < NCAND / RSUB; ++c) {
        const int j0 = g_cand[cbase + c];
#pragma unroll
        for (int e = 0; e < 2; ++e) {
            const int j = j0 + e;
            const ulonglong2* xj = (const ulonglong2*)(coords + (size_t)j * DIM);
            u64 acc = 0ull;
#pragma unroll
            for (int s = 0; s < DIM / 2; s += 2) {
                ulonglong2 v = xj[s >> 1];
                acc = ffma2(xi2[s], v.x, acc);
                acc = ffma2(xi2[s + 1], v.y, acc);
            }
            const float dot = pairsum(acc);
            float d = fmaf(-2.f, dot, base_i + g_sq[j]);
            if (j == row) d += DIAG_BIAS;   // pairs may reintroduce self
            if (d < vals[KNN - 1] || (d == vals[KNN - 1] && j < idx[KNN - 1]))
                topk_insert_tie(vals, idx, d, j);
        }
    }

    // publish partial top-16 lists
    {
        float* pv = sv + (rloc * RSUB + sub) * KNN;
        int*   px = sx + (rloc * RSUB + sub) * KNN;
#pragma unroll
        for (int t = 0; t < KNN; ++t) { pv[t] = vals[t]; px[t] = idx[t]; }
    }
    __syncthreads();

    if (sub == 0) {
#pragma unroll
        for (int p = 1; p < RSUB; ++p) {
            const float* pv = sv + (rloc * RSUB + p) * KNN;
            const int*   px = sx + (rloc * RSUB + p) * KNN;
#pragma unroll
            for (int k = 0; k < KNN; ++k) {
                float v = pv[k];
                int   j = px[k];
                if (v < vals[KNN - 1] || (v == vals[KNN - 1] && j < idx[KNN - 1]))
                    topk_insert_tie(vals, idx, v, j);
            }
        }
        const float inv = g_sigma_inv;
        const float vi  = potential[row];
        float lap = 0.f;
#pragma unroll
        for (int t = 0; t < KNN; ++t) {
            float w = expf(-vals[t] * inv);
            lap += w * (potential[idx[t]] - vi);
        }
        out[row] = lap;
    }
}

// ---------------------------------------------------------------------------
extern "C" void kernel_launch(void* const* d_in, const int* in_sizes, int n_in,
                              void* d_out, int out_size) {
    const float* coords    = (const float*)d_in[0];
    const float* potential = (const float*)d_in[1];
    float* out = (float*)d_out;

    cudaFuncSetAttribute(knn_mma_kernel,
                         cudaFuncAttributeMaxDynamicSharedMemorySize,
                         SMEM_BYTES);

    // knn_mma_kernel kept as the 4th launch -> it is the kernel ncu captures.
    hi_kernel<<<NPTS * DIM / 256, 256>>>(coords);     // 1
    sq_kernel<<<NPTS / 256, 256>>>(coords);           // 2
    colsum_kernel<<<DIM, 256>>>(coords);              // 3
    dim3 grid(NROWBLK, NSEG);
    knn_mma_kernel<<<grid, THREADS, SMEM_BYTES>>>();  // 4  <- profiled
    sqsum_kernel<<<48, 256>>>();                      // 5
    sigma_final_kernel<<<1, 32>>>();                  // 6
    rescore_lap_kernel<<<NPTS / 16, 128>>>(coords, potential, out);  // 7
}

// round 15
// speedup vs baseline: 2.3924x; 2.3924x over previous
#include <cuda_runtime.h>
#include <float.h>
#include <math.h>
#include <stdint.h>

// Problem constants
#define NPTS 12288
#define DIM 64
#define KNN 16
#define EPS 1e-5f
#define DIAG_BIAS 1e6f

// Tiling: 256 threads (8 warps x m16), BI=128 rows, BJ=64 cols per tile
#define THREADS 256
#define BI 128
#define BJ 64
#define NSEG 3
#define SEGJ (NPTS / NSEG)        // 4096
#define NTILES (SEGJ / BJ)        // 64
#define NROWBLK (NPTS / BI)       // 96
#define CPSEG 16                  // merged pair-entries per (row, segment)
#define NCAND (NSEG * CPSEG)      // 48 pair-entries per row (96 candidates)
#define RSUB 4                    // rescore sub-threads per row

// smem layout (floats). sj holds hi-only j-tiles, permuted k order: [col][64].
#define SJ_STRIDE 72
#define SJ_BUF (BJ * SJ_STRIDE)                      // 4608
#define SSQJ_OFF (2 * SJ_BUF)                        // 9216
#define SMEM_FLOATS (SSQJ_OFF + 2 * BJ)              // 9344
#define SMEM_BYTES (SMEM_FLOATS * 4)                 // 37376
// merge buffer (reuses smem after mainloop): 8 warps x 16 rows x 68 uints
#define MROW 68

// Scratch (no allocations -> device globals)
__device__ float  g_hi[NPTS * DIM];   // tf32-rounded coords, permuted k order
__device__ float  g_sq[NPTS];
__device__ float  g_colsum[DIM];
__device__ double g_part[48];
__device__ float  g_sigma_inv;
__device__ int    g_cand[NPTS * NCAND];

typedef unsigned long long u64;

__device__ __forceinline__ uint32_t sptr(const void* p) {
    return (uint32_t)__cvta_generic_to_shared(p);
}
__device__ __forceinline__ void cp_async16(uint32_t dst, const void* src) {
    asm volatile("cp.async.cg.shared.global [%0], [%1], 16;" :: "r"(dst), "l"(src));
}
__device__ __forceinline__ void cp_async4(uint32_t dst, const void* src) {
    asm volatile("cp.async.ca.shared.global [%0], [%1], 4;" :: "r"(dst), "l"(src));
}
#define CP_COMMIT() asm volatile("cp.async.commit_group;")
#define CP_WAIT0()  asm volatile("cp.async.wait_group 0;")

// packed fp32x2 fma (R2's exact-scoring instruction)
__device__ __forceinline__ u64 ffma2(u64 a, u64 b, u64 c) {
    u64 d;
    asm("fma.rn.f32x2 %0, %1, %2, %3;" : "=l"(d) : "l"(a), "l"(b), "l"(c));
    return d;
}
__device__ __forceinline__ float pairsum(u64 a) {
    float lo = __uint_as_float((unsigned)(a & 0xffffffffull));
    float hi = __uint_as_float((unsigned)(a >> 32));
    return lo + hi;
}

// m16n8k8 tf32 mma: D = A*B + D (row-major A, col-major B), fp32 accum
__device__ __forceinline__ void mma_tf32(float (&c)[4], const uint32_t* a,
                                         uint32_t b0, uint32_t b1) {
    asm volatile(
        "mma.sync.aligned.m16n8k8.row.col.f32.tf32.tf32.f32 "
        "{%0,%1,%2,%3}, {%4,%5,%6,%7}, {%8,%9}, {%0,%1,%2,%3};"
        : "+f"(c[0]), "+f"(c[1]), "+f"(c[2]), "+f"(c[3])
        : "r"(a[0]), "r"(a[1]), "r"(a[2]), "r"(a[3]), "r"(b0), "r"(b1));
}

// ---------------------------------------------------------------------------
// Prologue: tf32-round coords into g_hi with permuted k order.
// ---------------------------------------------------------------------------
__global__ void hi_kernel(const float* __restrict__ coords) {
    int i = blockIdx.x * 256 + threadIdx.x;   // 0 .. NPTS*DIM-1
    int row = i >> 6, k = i & 63;
    int kc = k >> 3, r = k & 7;
    int pos = kc * 8 + (r & 3) * 2 + (r >> 2);
    float x = coords[i];
    uint32_t h;
    asm("cvt.rna.tf32.f32 %0, %1;" : "=r"(h) : "f"(x));
    g_hi[row * DIM + pos] = __uint_as_float(h);
}

// ---------------------------------------------------------------------------
__global__ void sq_kernel(const float* __restrict__ coords) {
    int row = blockIdx.x * 256 + threadIdx.x;
    const float4* p = (const float4*)(coords + (size_t)row * DIM);
    float s = 0.f;
#pragma unroll
    for (int t = 0; t < DIM / 4; ++t) {
        float4 v = p[t];
        s += v.x * v.x + v.y * v.y + v.z * v.z + v.w * v.w;
    }
    g_sq[row] = s;
}

__global__ void colsum_kernel(const float* __restrict__ coords) {
    __shared__ float red[256];
    int d = blockIdx.x;
    float s = 0.f;
    for (int r = threadIdx.x; r < NPTS; r += 256)
        s += coords[(size_t)r * DIM + d];
    red[threadIdx.x] = s;
    __syncthreads();
    for (int off = 128; off > 0; off >>= 1) {
        if (threadIdx.x < off) red[threadIdx.x] += red[threadIdx.x + off];
        __syncthreads();
    }
    if (threadIdx.x == 0) g_colsum[d] = red[0];
}

// 48 partial double sums of g_sq (deterministic tree per block)
__global__ void sqsum_kernel() {
    __shared__ double red[256];
    double s = (double)g_sq[blockIdx.x * 256 + threadIdx.x];
    red[threadIdx.x] = s;
    __syncthreads();
    for (int off = 128; off > 0; off >>= 1) {
        if (threadIdx.x < off) red[threadIdx.x] += red[threadIdx.x + off];
        __syncthreads();
    }
    if (threadIdx.x == 0) g_part[blockIdx.x] = red[0];
}

__global__ void sigma_final_kernel() {
    if (threadIdx.x == 0) {
        double sumsq = 0.0;
        for (int i = 0; i < 48; ++i) sumsq += g_part[i];
        double nrm2 = 0.0;
        for (int d = 0; d < DIM; ++d) {
            double c = (double)g_colsum[d];
            nrm2 += c * c;
        }
        const double Nd = (double)NPTS;
        double total = 2.0 * Nd * sumsq - 2.0 * nrm2
                     + Nd * Nd * (double)EPS + Nd * (double)DIAG_BIAS;
        double sigma2 = total / (Nd * Nd);
        g_sigma_inv = (float)(1.0 / (sigma2 + (double)EPS));
    }
}

// lexicographic (value, index) sorted insert (exact selection semantics)
__device__ __forceinline__ void topk_insert_tie(float (&vals)[KNN],
                                                int (&idx)[KNN],
                                                float v, int id) {
#pragma unroll
    for (int t = 0; t < KNN; ++t) {
        bool lt = (v < vals[t]) || (v == vals[t] && id < idx[t]);
        if (lt) {
            float tv = vals[t]; vals[t] = v; v = tv;
            int   ti = idx[t];  idx[t]  = id; id = ti;
        }
    }
}

// register key-list insert: sorted ascending, 16 deep, straight min/max chain.
// Caller guarantees k < ks[15].
__device__ __forceinline__ void key_insert(uint32_t (&ks)[16], uint32_t k) {
#pragma unroll
    for (int t = 0; t < 16; ++t) {
        uint32_t cur = ks[t];
        uint32_t lo = (k < cur) ? k : cur;
        uint32_t hi = (k < cur) ? cur : k;
        ks[t] = lo;
        k = hi;
    }
}

// ---------------------------------------------------------------------------
// Stage one 64-row hi-only j-tile (256B per row, direct copy of g_hi rows).
// ---------------------------------------------------------------------------
__device__ __forceinline__ void issue_jtile(int jbase, float* sjb,
                                            float* ssqjb, int tid) {
    int r = tid >> 2;        // 0..63 tile row
    int c4 = tid & 3;
    const float* src = g_hi + (size_t)(jbase + r) * DIM;
    float* dst = sjb + r * SJ_STRIDE;
#pragma unroll
    for (int m = 0; m < 4; ++m) {
        int ch = c4 + m * 4;  // 16B chunk 0..15
        cp_async16(sptr(dst + ch * 4), src + ch * 4);
    }
    if (tid < BJ) cp_async4(sptr(ssqjb + tid), &g_sq[jbase + tid]);
}

// ---------------------------------------------------------------------------
// Kernel B: single-tf32 tensor-core distance tiles + register-packed top-16
// over COLUMN-PAIR MINIMA, then an in-kernel merge of the 4 lane-lists per
// row (global top-16 pairs per row-segment still contain all top-16 singles:
// every better-ranked pair holds an element smaller than x; at most 15 exist).
// ---------------------------------------------------------------------------
__global__ void __launch_bounds__(THREADS, 2)
knn_mma_kernel() {
    extern __shared__ float smem[];
    float* sj   = smem;
    float* ssqj = smem + SSQJ_OFF;

    const int tid = threadIdx.x;
    const int w = tid >> 5, l = tid & 31;
    const int g = l >> 2, t = l & 3;
    const int row0 = blockIdx.x * BI;
    const int jseg = blockIdx.y * SEGJ;
    const int rowA0 = row0 + w * 16 + g;
    const int rowA1 = rowA0 + 8;

    // warp-uniform: the single tile (if any) containing this warp's diagonal
    int diagTile = -1;
    if (rowA0 >= jseg && rowA0 < jseg + SEGJ) diagTile = (rowA0 - jseg) >> 6;

    uint32_t key0[16], key1[16];
#pragma unroll
    for (int k = 0; k < 16; ++k) { key0[k] = 0xFFFFFFFFu; key1[k] = 0xFFFFFFFFu; }

    // A fragments (persistent, hi only)
    uint32_t ah[32];
#pragma unroll
    for (int kc = 0; kc < 8; ++kc) {
        float2 p0 = *(const float2*)&g_hi[(size_t)rowA0 * DIM + kc * 8 + 2 * t];
        float2 p1 = *(const float2*)&g_hi[(size_t)rowA1 * DIM + kc * 8 + 2 * t];
        ah[kc * 4 + 0] = __float_as_uint(p0.x);
        ah[kc * 4 + 1] = __float_as_uint(p1.x);
        ah[kc * 4 + 2] = __float_as_uint(p0.y);
        ah[kc * 4 + 3] = __float_as_uint(p1.y);
    }
    const float sqi0e = g_sq[rowA0] + EPS;
    const float sqi1e = g_sq[rowA1] + EPS;

    issue_jtile(jseg, sj, ssqj, tid);
    CP_COMMIT();

    int buf = 0;
    for (int tile = 0; tile < NTILES; ++tile) {
        const int jbase = jseg + tile * BJ;
        CP_WAIT0();
        __syncthreads();

        if (tile + 1 < NTILES) {
            issue_jtile(jbase + BJ, sj + (buf ^ 1) * SJ_BUF,
                        ssqj + (buf ^ 1) * BJ, tid);
            CP_COMMIT();
        }

        const float* sjb = sj + buf * SJ_BUF;
        const float* ssqjb = ssqj + buf * BJ;
        const bool diagHere = (tile == diagTile);
#pragma unroll
        for (int nt2 = 0; nt2 < 4; ++nt2) {
            float c0[4] = {0.f, 0.f, 0.f, 0.f};
            float c1[4] = {0.f, 0.f, 0.f, 0.f};
            const float* b0p = sjb + (nt2 * 16 + g) * SJ_STRIDE + 2 * t;
            const float* b1p = sjb + (nt2 * 16 + 8 + g) * SJ_STRIDE + 2 * t;
#pragma unroll
            for (int kc = 0; kc < 8; ++kc) {
                float2 b0 = *(const float2*)(b0p + kc * 8);  // (k=t, k=t+4)
                float2 b1 = *(const float2*)(b1p + kc * 8);
                mma_tf32(c0, ah + kc * 4, __float_as_uint(b0.x), __float_as_uint(b0.y));
                mma_tf32(c1, ah + kc * 4, __float_as_uint(b1.x), __float_as_uint(b1.y));
            }
#pragma unroll
            for (int h = 0; h < 2; ++h) {
                const float* c = h ? c1 : c0;
                const int nt = nt2 * 2 + h;
                const int colb = nt * 8 + 2 * t;
                float2 sqj2 = *(const float2*)(ssqjb + colb);
                float d0 = fmaf(-2.f, c[0], sqi0e + sqj2.x);
                float d1 = fmaf(-2.f, c[1], sqi0e + sqj2.y);
                float d2 = fmaf(-2.f, c[2], sqi1e + sqj2.x);
                float d3 = fmaf(-2.f, c[3], sqi1e + sqj2.y);
                if (diagHere) {           // warp-uniform, one tile per segment
                    const int col0 = jbase + colb;
                    if (rowA0 == col0)     d0 += DIAG_BIAS;
                    if (rowA0 == col0 + 1) d1 += DIAG_BIAS;
                    if (rowA1 == col0)     d2 += DIAG_BIAS;
                    if (rowA1 == col0 + 1) d3 += DIAG_BIAS;
                }
                const uint32_t cin0 = (uint32_t)(tile * BJ + colb);  // even
                uint32_t k0 = (__float_as_uint(fminf(d0, d1)) & 0xFFFFF000u) | cin0;
                if (k0 < key0[15]) key_insert(key0, k0);
                uint32_t k1 = (__float_as_uint(fminf(d2, d3)) & 0xFFFFF000u) | cin0;
                if (k1 < key1[15]) key_insert(key1, k1);
            }
        }
        buf ^= 1;
    }

    // ---- in-kernel merge: 4 lane-lists -> top-16 pairs per row-segment ----
    __syncthreads();                       // sj/ssqj dead; reuse as merge buf
    uint32_t* kbuf = (uint32_t*)smem;
    uint32_t* wb = kbuf + w * (16 * MROW); // per-warp region
    {
#pragma unroll
        for (int k = 0; k < 16; ++k) {
            wb[g * MROW + t * 16 + k]       = key0[k];
            wb[(8 + g) * MROW + t * 16 + k] = key1[k];
        }
    }
    __syncwarp();
    if (l < 16) {
        const uint32_t* rb = wb + l * MROW;
        uint32_t mk[16];
#pragma unroll
        for (int k = 0; k < 16; ++k) mk[k] = rb[k];       // t = 0 list
#pragma unroll
        for (int p = 1; p < 4; ++p) {
#pragma unroll
            for (int k = 0; k < 16; ++k) {
                uint32_t c = rb[p * 16 + k];
                if (c < mk[15]) key_insert(mk, c);
            }
        }
        const int grow = row0 + w * 16 + l;
        const size_t o = ((size_t)grow * NSEG + blockIdx.y) * CPSEG;
#pragma unroll
        for (int k = 0; k < 16; ++k)
            g_cand[o + k] = jseg + (int)(mk[k] & 0xFFFu);
    }
}

// ---------------------------------------------------------------------------
// Kernel C: exact rescore. 4 sub-threads per row, each scoring 12 pair-entries
// (24 candidates) with R2's EXACT arithmetic; self-column guarded by
// DIAG_BIAS. Exact lexicographic merge in smem.
// ---------------------------------------------------------------------------
__global__ void __launch_bounds__(128)
rescore_lap_kernel(const float* __restrict__ coords,
                   const float* __restrict__ potential,
                   float* __restrict__ out) {
    __shared__ float sv[32 * RSUB * KNN];   // 2048 floats
    __shared__ int   sx[32 * RSUB * KNN];

    const int rloc = threadIdx.x >> 2;    // 0..31
    const int sub  = threadIdx.x & (RSUB - 1);
    const int row  = blockIdx.x * 32 + rloc;

    u64 xi2[DIM / 2];
    {
        const u64* p = (const u64*)(coords + (size_t)row * DIM);
#pragma unroll
        for (int s = 0; s < DIM / 2; ++s) xi2[s] = p[s];
    }
    const float base_i = g_sq[row] + EPS;

    float vals[KNN];
    int   idx[KNN];
#pragma unroll
    for (int t = 0; t < KNN; ++t) { vals[t] = FLT_MAX; idx[t] = 0x7fffffff; }

    const size_t cbase = (size_t)row * NCAND + sub * (NCAND / RSUB);
#pragma unroll 1
    for (int c = 0; c < NCAND / RSUB; ++c) {
        const int j0 = g_cand[cbase + c];
#pragma unroll
        for (int e = 0; e < 2; ++e) {
            const int j = j0 + e;
            const ulonglong2* xj = (const ulonglong2*)(coords + (size_t)j * DIM);
            u64 acc = 0ull;
#pragma unroll
            for (int s = 0; s < DIM / 2; s += 2) {
                ulonglong2 v = xj[s >> 1];
                acc = ffma2(xi2[s], v.x, acc);
                acc = ffma2(xi2[s + 1], v.y, acc);
            }
            const float dot = pairsum(acc);
            float d = fmaf(-2.f, dot, base_i + g_sq[j]);
            if (j == row) d += DIAG_BIAS;   // pairs may reintroduce self
            if (d < vals[KNN - 1] || (d == vals[KNN - 1] && j < idx[KNN - 1]))
                topk_insert_tie(vals, idx, d, j);
        }
    }

    // publish partial top-16 lists
    {
        float* pv = sv + (rloc * RSUB + sub) * KNN;
        int*   px = sx + (rloc * RSUB + sub) * KNN;
#pragma unroll
        for (int t = 0; t < KNN; ++t) { pv[t] = vals[t]; px[t] = idx[t]; }
    }
    __syncthreads();

    if (sub == 0) {
#pragma unroll
        for (int p = 1; p < RSUB; ++p) {
            const float* pv = sv + (rloc * RSUB + p) * KNN;
            const int*   px = sx + (rloc * RSUB + p) * KNN;
#pragma unroll
            for (int k = 0; k < KNN; ++k) {
                float v = pv[k];
                int   j = px[k];
                if (v < vals[KNN - 1] || (v == vals[KNN - 1] && j < idx[KNN - 1]))
                    topk_insert_tie(vals, idx, v, j);
            }
        }
        const float inv = g_sigma_inv;
        const float vi  = potential[row];
        float lap = 0.f;
#pragma unroll
        for (int t = 0; t < KNN; ++t) {
            float w = expf(-vals[t] * inv);
            lap += w * (potential[idx[t]] - vi);
        }
        out[row] = lap;
    }
}

// ---------------------------------------------------------------------------
extern "C" void kernel_launch(void* const* d_in, const int* in_sizes, int n_in,
                              void* d_out, int out_size) {
    const float* coords    = (const float*)d_in[0];
    const float* potential = (const float*)d_in[1];
    float* out = (float*)d_out;

    cudaFuncSetAttribute(knn_mma_kernel,
                         cudaFuncAttributeMaxDynamicSharedMemorySize,
                         SMEM_BYTES);

    // knn_mma_kernel kept as the 4th launch -> it is the kernel ncu captures.
    hi_kernel<<<NPTS * DIM / 256, 256>>>(coords);     // 1
    sq_kernel<<<NPTS / 256, 256>>>(coords);           // 2
    colsum_kernel<<<DIM, 256>>>(coords);              // 3
    dim3 grid(NROWBLK, NSEG);
    knn_mma_kernel<<<grid, THREADS, SMEM_BYTES>>>();  // 4  <- profiled
    sqsum_kernel<<<48, 256>>>();                      // 5
    sigma_final_kernel<<<1, 32>>>();                  // 6
    rescore_lap_kernel<<<NPTS / 32, 128>>>(coords, potential, out);  // 7
}